// round 15
// baseline (speedup 1.0000x reference)
#include <cuda_runtime.h>
#include <math_constants.h>

#define BATCH 32
#define NROWS 4096
#define HDIM  256
#define H4    (HDIM / 4)          // 64 float4 per row
#define NGRP  512
#define KIDX  16
#define NOUT_IDX (NGRP * KIDX)    // 8192
#define NBLK  1024                // grid size; MUST be <= resident capacity (1184)

// scratch: per-(row, channel) max over batch. 4 MB, alloc-free.
__device__ float4 g_bmax[NROWS * H4];
// rows referenced by idx this call (reset in phase 3 for the next replay)
__device__ unsigned char g_mask[NROWS];
// monotonic grid-barrier counter (never reset; replay-safe, deterministic)
__device__ unsigned int g_bar;

__device__ __forceinline__ void fmax4(float4& m, const float4 v) {
    m.x = fmaxf(m.x, v.x);
    m.y = fmaxf(m.y, v.y);
    m.z = fmaxf(m.z, v.z);
    m.w = fmaxf(m.w, v.w);
}

// Grid-wide barrier for a fully-resident grid of exactly NBLK CTAs.
// Monotonic ticket counter: each use advances one NBLK-window; all CTAs of
// one use spin for the same target. Safe across graph replays (no reset).
__device__ __forceinline__ void grid_barrier() {
    __syncthreads();
    if (threadIdx.x == 0) {
        __threadfence();                          // prior stores visible first
        unsigned int old = atomicAdd(&g_bar, 1u);
        unsigned int target = (old / NBLK + 1u) * NBLK;
        while (true) {
            unsigned int v;
            asm volatile("ld.acquire.gpu.u32 %0, [%1];"
                         : "=r"(v) : "l"(&g_bar) : "memory");
            if (v >= target) break;
            __nanosleep(64);
        }
    }
    __syncthreads();
}

// One persistent kernel, three phases:
//  P1: build row mask from idx
//  P2: bmax[a][h] = max_b x[b,a,h] for flagged rows (the 114 MB stream)
//  P3: out[g][h] = max_{k<16} bmax[idx[g,k]][h]  (bmax is L2-hot: just written)
__global__ __launch_bounds__(256, 8) void fused_kernel(
        const float4* __restrict__ x, const int* __restrict__ idx,
        float4* __restrict__ out) {
    const int tid = threadIdx.x;
    const int i   = blockIdx.x * 256 + tid;      // 0 .. 262143

    // ---- Phase 1: flag referenced rows (benign races, all write 1) ----
    if (i < NOUT_IDX) g_mask[idx[i]] = 1;

    grid_barrier();

    // ---- Phase 2: masked batch-max stream ----
    const int row = i >> 6;
    if (__ldcg(&g_mask[row])) {
        const float4* p = x + i;
        float4 m = make_float4(-CUDART_INF_F, -CUDART_INF_F, -CUDART_INF_F, -CUDART_INF_F);
        #pragma unroll 8
        for (int b = 0; b < BATCH; ++b)
            fmax4(m, p[(size_t)b * (NROWS * H4)]);
        g_bmax[i] = m;
    }

    grid_barrier();

    // ---- Phase 3 ----
    const int blk = blockIdx.x;
    if (blk < NGRP) {
        // one group per CTA: 4 K-subsets x 64 chunks, smem tree-reduce
        __shared__ int sidx[KIDX];
        if (tid < KIDX) sidx[tid] = idx[blk * KIDX + tid];
        __syncthreads();

        const int k4 = tid >> 6;         // 0..3 : which 4 indices
        const int c  = tid & 63;         // 0..63: float4 chunk

        float4 m = make_float4(-CUDART_INF_F, -CUDART_INF_F, -CUDART_INF_F, -CUDART_INF_F);
        #pragma unroll
        for (int k = k4 * 4; k < k4 * 4 + 4; ++k) {
            const float4* q = &g_bmax[sidx[k] * H4 + c];
            float4 v;
            v.x = __ldcg(&q->x); v.y = __ldcg(&q->y);
            v.z = __ldcg(&q->z); v.w = __ldcg(&q->w);
            fmax4(m, v);
        }

        __shared__ float4 s[256];
        s[tid] = m;
        __syncthreads();

        if (k4 == 0) {
            #pragma unroll
            for (int j = 1; j < 4; ++j)
                fmax4(m, s[j * 64 + c]);
            out[blk * H4 + c] = m;
        }
    } else if (blk < NGRP + 16) {
        // reset mask for the next graph replay (16 CTAs x 256 = 4096 rows)
        g_mask[(blk - NGRP) * 256 + tid] = 0;
    }
}

extern "C" void kernel_launch(void* const* d_in, const int* in_sizes, int n_in,
                              void* d_out, int out_size) {
    const float4* x = (const float4*)d_in[0];   // (32, 4096*256) fp32
    const int*  idx = (const int*)d_in[1];      // (512, 16) int32
    float4*     out = (float4*)d_out;           // 512*256 fp32 = 2048 float4

    fused_kernel<<<NBLK, 256>>>(x, idx, out);
    (void)in_sizes; (void)n_in; (void)out_size;
}

// round 16
// speedup vs baseline: 1.3728x; 1.3728x over previous
#include <cuda_runtime.h>
#include <math_constants.h>

#define BATCH 32
#define NROWS 4096
#define HDIM  256
#define H4    (HDIM / 4)          // 64 float4 per row
#define NGRP  512
#define KIDX  16
#define NOUT_IDX (NGRP * KIDX)    // 8192

// scratch: per-(row, channel) max over batch. 4 MB, alloc-free.
__device__ float4 g_bmax[NROWS * H4];
// rows referenced by idx this call (zeroed by groupmax for the next call)
__device__ unsigned char g_mask[NROWS];

__device__ __forceinline__ void fmax4(float4& m, const float4 v) {
    m.x = fmaxf(m.x, v.x);
    m.y = fmaxf(m.y, v.y);
    m.z = fmaxf(m.z, v.z);
    m.w = fmaxf(m.w, v.w);
}

// Kernel 0: flag referenced rows. Benign write races (all write 1).
__global__ __launch_bounds__(256) void set_mask_kernel(const int* __restrict__ idx) {
    const int i = blockIdx.x * blockDim.x + threadIdx.x;
    if (i < NOUT_IDX) g_mask[idx[i]] = 1;
    cudaTriggerProgrammaticLaunchCompletion();
}

// Kernel 1: bmax[a][h] = max over 32 batches of x[b,a,h], flagged rows only
// (~13.5% of rows are never gathered). One thread per (row, float4-chunk),
// fully coalesced streaming reads, batch stride 4 MB. PDL: wait for mask.
__global__ __launch_bounds__(256) void batchmax_kernel(const float4* __restrict__ x) {
    const int i   = blockIdx.x * blockDim.x + threadIdx.x;   // 0 .. NROWS*H4-1
    const int row = i >> 6;

    cudaGridDependencySynchronize();          // mask is ready

    if (g_mask[row]) {
        const float4* p = x + i;
        float4 m = make_float4(-CUDART_INF_F, -CUDART_INF_F, -CUDART_INF_F, -CUDART_INF_F);
        #pragma unroll 8
        for (int b = 0; b < BATCH; ++b)
            fmax4(m, p[(size_t)b * (NROWS * H4)]);
        g_bmax[i] = m;
    }
    cudaTriggerProgrammaticLaunchCompletion(); // after this CTA's stores
}

// Kernel 2: out[g][h] = max over the 16 rows idx[g,k] of bmax[row][h].
// 512 threads per group: 8 K-subsets x 64 chunks -> each thread only 2
// independent gathers (vs 4 before, with 2x the warps chip-wide), then an
// 8-way smem tree-reduce. Also resets g_mask for the next replay.
__global__ __launch_bounds__(512) void groupmax_kernel(const int* __restrict__ idx,
                                                       float4* __restrict__ out) {
    const int g   = blockIdx.x;
    const int tid = threadIdx.x;

    cudaGridDependencySynchronize();          // bmax + mask reads are done

    // reset mask for next call (first 8 blocks cover all 4096 rows)
    const int gt = g * 512 + tid;
    if (gt < NROWS) g_mask[gt] = 0;

    __shared__ int sidx[KIDX];
    if (tid < KIDX) sidx[tid] = idx[g * KIDX + tid];
    __syncthreads();

    const int k8 = tid >> 6;         // 0..7 : which pair of indices
    const int c  = tid & 63;         // 0..63: float4 chunk

    const int r0 = sidx[k8 * 2 + 0];
    const int r1 = sidx[k8 * 2 + 1];
    float4 m = g_bmax[r0 * H4 + c];
    fmax4(m, g_bmax[r1 * H4 + c]);

    __shared__ float4 s[512];
    s[tid] = m;
    __syncthreads();

    if (k8 == 0) {
        #pragma unroll
        for (int j = 1; j < 8; ++j)
            fmax4(m, s[j * 64 + c]);
        out[g * H4 + c] = m;
    }
}

static inline void launch_pdl(void* fn, dim3 grid, dim3 block, void** args) {
    cudaLaunchConfig_t cfg = {};
    cfg.gridDim  = grid;
    cfg.blockDim = block;
    cfg.stream   = 0;
    cudaLaunchAttribute attr[1];
    attr[0].id = cudaLaunchAttributeProgrammaticStreamSerialization;
    attr[0].val.programmaticStreamSerializationAllowed = 1;
    cfg.attrs    = attr;
    cfg.numAttrs = 1;
    cudaLaunchKernelExC(&cfg, fn, args);
}

extern "C" void kernel_launch(void* const* d_in, const int* in_sizes, int n_in,
                              void* d_out, int out_size) {
    const float4* x = (const float4*)d_in[0];   // (32, 4096*256) fp32
    const int*  idx = (const int*)d_in[1];      // (512, 16) int32
    float4*     out = (float4*)d_out;           // 512*256 fp32 = 2048 float4

    set_mask_kernel<<<NOUT_IDX / 256, 256>>>(idx);
    {
        void* args[] = { (void*)&x };
        launch_pdl((void*)batchmax_kernel, dim3((NROWS * H4) / 256), dim3(256), args);
    }
    {
        void* args[] = { (void*)&idx, (void*)&out };
        launch_pdl((void*)groupmax_kernel, dim3(NGRP), dim3(512), args);
    }
    (void)in_sizes; (void)n_in; (void)out_size;
}